// round 4
// baseline (speedup 1.0000x reference)
#include <cuda_runtime.h>
#include <cuda_bf16.h>
#include <cstdint>
#include <cstddef>

#define T_ 512
#define N_ 512
#define B_ 128
#define W1 513      // N+1 (weight row length)
#define NBLK 128
#define NTHR 256

// shared memory layout (floats)
#define SM_WI   0
#define SM_WH   16416
#define SM_CS   32832
#define SM_HS   41024
#define SM_WF   49216
#define SM_BIAS 49248
#define SM_W0   49280
#define SM_XB   49312
#define SM_FS   49328
#define SM_RED  49344
#define SM_FLOATS 49856
#define SMEM_BYTES (SM_FLOATS * 4)   // 199,424 B

// device scratch (static arrays: allocation-free)
__device__ float g_AT[(size_t)T_ * N_ * N_];   // A transposed: [t][j][i]
__device__ float g_c[2][(size_t)B_ * N_];      // double-buffered c-hat, [b][j]
__device__ float g_fp[2][B_ * 16];             // f partials: [parity][b][i_tile]
__device__ float g_fbase[T_ * B_];             // bf + Wf0 * x[b,t]
__device__ unsigned g_arrive;
__device__ volatile unsigned g_gen;

__device__ __forceinline__ void grid_barrier() {
    __syncthreads();
    if (threadIdx.x == 0) {
        unsigned old = g_gen;
        __threadfence();
        if (atomicAdd(&g_arrive, 1u) == (unsigned)(NBLK - 1)) {
            atomicExch(&g_arrive, 0u);
            __threadfence();
            g_gen = old + 1u;
        } else {
            while (g_gen == old) { }
        }
    }
    __syncthreads();
    __threadfence();
}

// ---------------------------------------------------------------------------
// Pre-pass 1: transpose A_stack[t][i][j] -> g_AT[t][j][i]
// grid (16,16,512), block (32,8)
// ---------------------------------------------------------------------------
__global__ void k_transpose(const float* __restrict__ A) {
    __shared__ float tile[32][33];
    int t  = blockIdx.z;
    int j0 = blockIdx.x << 5, i0 = blockIdx.y << 5;
    int tx = threadIdx.x, ty = threadIdx.y;
    const float* src = A + ((size_t)t * N_ + i0) * N_ + j0;
#pragma unroll
    for (int r = 0; r < 4; ++r)
        tile[ty + r * 8][tx] = src[(size_t)(ty + r * 8) * N_ + tx];
    __syncthreads();
    float* dst = g_AT + ((size_t)t * N_ + j0) * N_ + i0;
#pragma unroll
    for (int r = 0; r < 4; ++r)
        dst[(size_t)(ty + r * 8) * N_ + tx] = tile[tx][ty + r * 8];
}

// ---------------------------------------------------------------------------
// Pre-pass 2: per-launch re-init of mutable state (graph-replay safe)
// ---------------------------------------------------------------------------
__global__ void k_init(const float* __restrict__ x, const float* __restrict__ c0,
                       const float* __restrict__ Wf, const float* __restrict__ bf) {
    int idx = blockIdx.x * blockDim.x + threadIdx.x;
    if (idx < B_ * N_) g_c[0][idx] = c0[idx];          // (B,N) b-major, direct copy
    if (idx < T_ * B_) {
        int t = idx >> 7, b = idx & 127;
        g_fbase[idx] = __ldg(&bf[0]) + __ldg(&Wf[0]) * __ldg(&x[(size_t)b * T_ + t]);
    }
    if (idx < B_ * 16) g_fp[1][idx] = 0.0f;            // f_{-1} partials = 0
}

// ---------------------------------------------------------------------------
// Main persistent kernel: 128 blocks x 256 threads.
// block = (it in [0,16): i-tile of 32 columns) x (bt in [0,8): batch tile of 16)
// ---------------------------------------------------------------------------
__global__ void __launch_bounds__(NTHR, 1)
hippo_main(const float* __restrict__ x,  const float* __restrict__ h0,
           const float* __restrict__ Wi, const float* __restrict__ bi,
           const float* __restrict__ Wh, const float* __restrict__ bh,
           const float* __restrict__ Wf, const float* __restrict__ B_st,
           float* __restrict__ out) {
    extern __shared__ float sm[];
    float* Wi_s   = sm + SM_WI;    // [32][513] padded rows -> conflict-free
    float* Wh_s   = sm + SM_WH;
    float* cs     = sm + SM_CS;    // [512 j][16 b]  c_eff = c-hat + f*B
    float* hsm    = sm + SM_HS;    // [512 j][16 b]  h_{t-1}
    float* wf_s   = sm + SM_WF;
    float* bias_s = sm + SM_BIAS;
    float* w0_s   = sm + SM_W0;
    float* xb     = sm + SM_XB;
    float* fs     = sm + SM_FS;
    float* red    = sm + SM_RED;   // [16 b][32 i]

    const int tid = threadIdx.x;
    const int it  = blockIdx.x >> 3;   // i-tile 0..15
    const int bt  = blockIdx.x & 7;    // b-tile 0..7
    const int i0  = it << 5;
    const int bb0 = bt << 4;

    // one-time weight staging (reused for all 512 steps)
    for (int idx = tid; idx < 32 * 512; idx += NTHR) {
        int iL = idx >> 9, j = idx & 511;
        Wi_s[iL * W1 + j] = __ldg(&Wi[(size_t)(i0 + iL) * W1 + 1 + j]);
        Wh_s[iL * W1 + j] = __ldg(&Wh[(size_t)(i0 + iL) * W1 + 1 + j]);
    }
    if (tid < 32) {
        wf_s[tid]   = __ldg(&Wf[1 + i0 + tid]);
        bias_s[tid] = __ldg(&bi[i0 + tid]) + __ldg(&bh[i0 + tid]);
        w0_s[tid]   = __ldg(&Wi[(size_t)(i0 + tid) * W1]) + __ldg(&Wh[(size_t)(i0 + tid) * W1]);
    }
    __syncthreads();

    const int il   = tid & 31;   // compute role: i within tile
    const int bq   = tid >> 5;   // compute role: batch pair 0..7
    const int ig   = i0 + il;    // global i
    const int w    = tid >> 5;   // staging role: warp id
    const int lane = tid & 31;

    for (int t = 0; t < T_; ++t) {
        const int rpar = t & 1, wpar = rpar ^ 1;

        // --- reconstruct f_{t-1}[b] (deterministic 16-term sum) + stage x_t ---
        if (tid < 16) {
            int b = bb0 + tid;
            float f = 0.0f;
            if (t > 0) {
                f = g_fbase[(t - 1) * B_ + b];
                const float* fp = g_fp[rpar ^ 1] + b * 16;
#pragma unroll
                for (int k = 0; k < 16; ++k) f += __ldcg(&fp[k]);
            }
            fs[tid] = f;
            xb[tid] = __ldg(&x[(size_t)b * T_ + t]);
        }
        __syncthreads();

        // --- stage c_eff = c-hat + f*B_{t-1}, and h_{t-1}, into smem ---
        {
            int tb = (t > 0) ? (t - 1) : 0;
            const float* Bp = B_st + (size_t)tb * N_;
#pragma unroll
            for (int s2 = 0; s2 < 2; ++s2) {
                int bl = 2 * w + s2;
                int b  = bb0 + bl;
                const float* crow = g_c[rpar] + (size_t)b * N_;
                const float* hrow = (t == 0) ? (h0 + (size_t)b * N_)
                                             : (out + ((size_t)b * T_ + (t - 1)) * N_);
                float fb = fs[bl];
#pragma unroll 8
                for (int k = 0; k < 16; ++k) {
                    int j = k * 32 + lane;
                    cs[j * 16 + bl]  = __ldcg(&crow[j]) + fb * __ldg(&Bp[j]);
                    hsm[j * 16 + bl] = __ldcg(&hrow[j]);
                }
            }
        }
        __syncthreads();

        // --- main dots: gates (Wi*c + Wh*h) and c-hat_t = A_t * c_eff ---
        const float*  pA  = g_AT + (size_t)t * N_ * N_ + ig;
        const float2* cs2 = (const float2*)(cs + 2 * bq);   // broadcast across lanes
        const float2* hs2 = (const float2*)(hsm + 2 * bq);
        float ag0 = 0.f, ag1 = 0.f, aa0 = 0.f, aa1 = 0.f;
#pragma unroll 4
        for (int j = 0; j < N_; ++j) {
            float wi = Wi_s[il * W1 + j];
            float wh = Wh_s[il * W1 + j];
            float a  = __ldg(&pA[(size_t)j * N_]);
            float2 c2 = cs2[j * 8];
            float2 h2 = hs2[j * 8];
            ag0 = fmaf(wi, c2.x, ag0); ag0 = fmaf(wh, h2.x, ag0);
            ag1 = fmaf(wi, c2.y, ag1); ag1 = fmaf(wh, h2.y, ag1);
            aa0 = fmaf(a, c2.x, aa0);
            aa1 = fmaf(a, c2.y, aa1);
        }

        int bl0 = 2 * bq, bl1 = bl0 + 1;
        int b0g = bb0 + bl0, b1g = bb0 + bl1;
        float gate0 = bias_s[il] + w0_s[il] * xb[bl0] + ag0;
        float gate1 = bias_s[il] + w0_s[il] * xb[bl1] + ag1;
        float o0 = 1.0f / (1.0f + __expf(-gate0));
        float o1 = 1.0f / (1.0f + __expf(-gate1));
        float hn0 = o0 * tanhf(cs[ig * 16 + bl0]);
        float hn1 = o1 * tanhf(cs[ig * 16 + bl1]);

        out[((size_t)b0g * T_ + t) * N_ + ig] = hn0;
        out[((size_t)b1g * T_ + t) * N_ + ig] = hn1;
        red[bl0 * 32 + il] = wf_s[il] * hn0;
        red[bl1 * 32 + il] = wf_s[il] * hn1;
        __stcg(&g_c[wpar][(size_t)b0g * N_ + ig], aa0);
        __stcg(&g_c[wpar][(size_t)b1g * N_ + ig], aa1);
        __syncthreads();

        // --- per-block f partial (deterministic order) ---
        if (tid < 16) {
            float s = 0.0f;
#pragma unroll
            for (int k = 0; k < 32; ++k) s += red[tid * 32 + k];
            __stcg(&g_fp[t & 1][(bb0 + tid) * 16 + it], s);
        }

        if (t != T_ - 1) grid_barrier();
    }
}

// ---------------------------------------------------------------------------
// Final: c_f = c-hat_{511} + f_{511} * B_{511}, appended after hs in d_out
// ---------------------------------------------------------------------------
__global__ void k_final(const float* __restrict__ B_st, float* __restrict__ outc) {
    int idx = blockIdx.x * blockDim.x + threadIdx.x;
    if (idx >= B_ * N_) return;
    int b = idx >> 9, i = idx & 511;
    float f = g_fbase[(T_ - 1) * B_ + b];
#pragma unroll
    for (int k = 0; k < 16; ++k) f += g_fp[1][b * 16 + k];  // t=511 -> parity 1
    outc[idx] = g_c[0][idx] + f * __ldg(&B_st[(size_t)(T_ - 1) * N_ + i]);
}

extern "C" void kernel_launch(void* const* d_in, const int* in_sizes, int n_in,
                              void* d_out, int out_size) {
    const float* x  = (const float*)d_in[0];
    const float* h0 = (const float*)d_in[1];
    const float* c0 = (const float*)d_in[2];
    const float* Wi = (const float*)d_in[3];
    const float* bi = (const float*)d_in[4];
    const float* Wh = (const float*)d_in[5];
    const float* bh = (const float*)d_in[6];
    const float* Wf = (const float*)d_in[7];
    const float* bf = (const float*)d_in[8];
    const float* A  = (const float*)d_in[9];
    const float* Bs = (const float*)d_in[10];
    float* out = (float*)d_out;

    cudaFuncSetAttribute(hippo_main, cudaFuncAttributeMaxDynamicSharedMemorySize, SMEM_BYTES);

    k_transpose<<<dim3(16, 16, 512), dim3(32, 8)>>>(A);
    k_init<<<256, 256>>>(x, c0, Wf, bf);
    hippo_main<<<NBLK, NTHR, SMEM_BYTES>>>(x, h0, Wi, bi, Wh, bh, Wf, Bs, out);
    k_final<<<256, 256>>>(Bs, out + (size_t)B_ * T_ * N_);
}

// round 5
// speedup vs baseline: 3.0260x; 3.0260x over previous
#include <cuda_runtime.h>
#include <cuda_bf16.h>
#include <cstdint>
#include <cstddef>

#define T_ 512
#define N_ 512
#define B_ 128
#define W1 513
#define NBLK 128
#define NTHR 256

typedef unsigned long long ull;

// shared memory layout (float offsets)
#define SM_WIT  0         // [512 j][32 i]          16384
#define SM_WHT  16384     // [512 j][32 i]          16384
#define SM_CS   32768     // [512 j][18 pad] b<16    9216
#define SM_HS   41984     // [512 j][18 pad] b<16    9216
#define SM_RED  51200     // 512 ull (=1024 f)       1024
#define SM_REDF 52224     // [16 b][32 i]             512
#define SM_FS   52736     // 16
#define SM_XB   52752     // 16
#define SM_WF   52768     // 32
#define SM_BIAS 52800     // 32
#define SM_W0   52832     // 32
#define SM_FLOATS 52864
#define SMEM_BYTES (SM_FLOATS * 4)   // 211,456 B

// device scratch (static arrays: allocation-free)
__device__ float g_AT[(size_t)T_ * N_ * N_];   // A transposed: [t][j][i]
__device__ float g_WiT[(size_t)N_ * N_];       // Wi transposed: [j][i] (col 1..512)
__device__ float g_WhT[(size_t)N_ * N_];
__device__ float g_c[2][(size_t)B_ * N_];      // double-buffered c-hat, [b][j]
__device__ float g_fp[2][B_ * 16];             // f partials [parity][b][i_tile]
__device__ float g_fbase[T_ * B_];             // bf + Wf0 * x[b,t]
__device__ unsigned g_arrive;
__device__ volatile unsigned g_gen;

// ---- f32x2 helpers ----
__device__ __forceinline__ ull pack2(float a, float b) {
    ull r; asm("mov.b64 %0, {%1, %2};" : "=l"(r) : "f"(a), "f"(b)); return r;
}
__device__ __forceinline__ void unpack2(ull v, float& a, float& b) {
    asm("mov.b64 {%0, %1}, %2;" : "=f"(a), "=f"(b) : "l"(v));
}
__device__ __forceinline__ ull splat2(float a) {
    ull r; asm("mov.b64 %0, {%1, %1};" : "=l"(r) : "f"(a)); return r;
}
__device__ __forceinline__ ull fma2(ull a, ull b, ull c) {
    ull d; asm("fma.rn.f32x2 %0, %1, %2, %3;" : "=l"(d) : "l"(a), "l"(b), "l"(c)); return d;
}
__device__ __forceinline__ ull add2(ull a, ull b) {
    ull d; asm("add.rn.f32x2 %0, %1, %2;" : "=l"(d) : "l"(a), "l"(b)); return d;
}

__device__ __forceinline__ void grid_barrier() {
    __syncthreads();
    if (threadIdx.x == 0) {
        unsigned old = g_gen;
        __threadfence();
        if (atomicAdd(&g_arrive, 1u) == (unsigned)(NBLK - 1)) {
            atomicExch(&g_arrive, 0u);
            __threadfence();
            g_gen = old + 1u;
        } else {
            while (g_gen == old) { }
        }
    }
    __syncthreads();
    __threadfence();
}

// ---------------------------------------------------------------------------
// Pre-pass: transpose A_stack[t][i][j] -> g_AT[t][j][i]
// ---------------------------------------------------------------------------
__global__ void k_transpose(const float* __restrict__ A) {
    __shared__ float tile[32][33];
    int t  = blockIdx.z;
    int j0 = blockIdx.x << 5, i0 = blockIdx.y << 5;
    int tx = threadIdx.x, ty = threadIdx.y;
    const float* src = A + ((size_t)t * N_ + i0) * N_ + j0;
#pragma unroll
    for (int r = 0; r < 4; ++r)
        tile[ty + r * 8][tx] = src[(size_t)(ty + r * 8) * N_ + tx];
    __syncthreads();
    float* dst = g_AT + ((size_t)t * N_ + j0) * N_ + i0;
#pragma unroll
    for (int r = 0; r < 4; ++r)
        dst[(size_t)(ty + r * 8) * N_ + tx] = tile[tx][ty + r * 8];
}

// ---------------------------------------------------------------------------
// Pre-pass: transpose gate weights Wi/Wh[i][1+j] -> g_W*T[j][i]
// ---------------------------------------------------------------------------
__global__ void k_wtrans(const float* __restrict__ Wi, const float* __restrict__ Wh) {
    __shared__ float tile[32][33];
    const float* W = blockIdx.z ? Wh : Wi;
    float* WT = blockIdx.z ? g_WhT : g_WiT;
    int j0 = blockIdx.x << 5, i0 = blockIdx.y << 5;
    int tx = threadIdx.x, ty = threadIdx.y;
#pragma unroll
    for (int r = 0; r < 4; ++r)
        tile[ty + r * 8][tx] = W[(size_t)(i0 + ty + r * 8) * W1 + 1 + j0 + tx];
    __syncthreads();
#pragma unroll
    for (int r = 0; r < 4; ++r)
        WT[(size_t)(j0 + ty + r * 8) * N_ + i0 + tx] = tile[tx][ty + r * 8];
}

// ---------------------------------------------------------------------------
// Pre-pass: per-launch re-init of mutable state (graph-replay safe)
// ---------------------------------------------------------------------------
__global__ void k_init(const float* __restrict__ x, const float* __restrict__ c0,
                       const float* __restrict__ Wf, const float* __restrict__ bf) {
    int idx = blockIdx.x * blockDim.x + threadIdx.x;
    if (idx < B_ * N_) g_c[0][idx] = c0[idx];
    if (idx < T_ * B_) {
        int t = idx >> 7, b = idx & 127;
        g_fbase[idx] = __ldg(&bf[0]) + __ldg(&Wf[0]) * __ldg(&x[(size_t)b * T_ + t]);
    }
    if (idx < B_ * 16) g_fp[1][idx] = 0.0f;
}

// ---------------------------------------------------------------------------
// Main persistent kernel: 128 blocks x 256 threads.
// block = (it in [0,16): 32 i-cols) x (bt in [0,8): 16 batches)
// thread = kh (k-half) x bp (batch pair 0..7) x ip (i pair 0..15)
// ---------------------------------------------------------------------------
__global__ void __launch_bounds__(NTHR, 1)
hippo_main(const float* __restrict__ x,  const float* __restrict__ h0,
           const float* __restrict__ Wi, const float* __restrict__ bi,
           const float* __restrict__ Wh, const float* __restrict__ bh,
           const float* __restrict__ Wf, const float* __restrict__ B_st,
           float* __restrict__ out) {
    extern __shared__ float sm[];
    float* WiT_s  = sm + SM_WIT;
    float* WhT_s  = sm + SM_WHT;
    float* cs     = sm + SM_CS;    // c_eff, row stride 18
    float* hs     = sm + SM_HS;    // h_{t-1}, row stride 18
    ull*   red_u  = (ull*)(sm + SM_RED);
    float* redf   = sm + SM_REDF;
    float* fs     = sm + SM_FS;
    float* xb     = sm + SM_XB;
    float* wf_s   = sm + SM_WF;
    float* bias_s = sm + SM_BIAS;
    float* w0_s   = sm + SM_W0;

    const int tid = threadIdx.x;
    const int it  = blockIdx.x >> 3;   // i-tile 0..15
    const int bt  = blockIdx.x & 7;    // b-tile 0..7
    const int i0  = it << 5;
    const int bb0 = bt << 4;

    // one-time weight staging (transposed layout; coalesced LDG, conflict-free STS)
    for (int idx = tid; idx < 512 * 32; idx += NTHR) {
        int j = idx >> 5, iL = idx & 31;
        WiT_s[j * 32 + iL] = __ldg(&g_WiT[(size_t)j * N_ + i0 + iL]);
        WhT_s[j * 32 + iL] = __ldg(&g_WhT[(size_t)j * N_ + i0 + iL]);
    }
    if (tid < 32) {
        wf_s[tid]   = __ldg(&Wf[1 + i0 + tid]);
        bias_s[tid] = __ldg(&bi[i0 + tid]) + __ldg(&bh[i0 + tid]);
        w0_s[tid]   = __ldg(&Wi[(size_t)(i0 + tid) * W1]) + __ldg(&Wh[(size_t)(i0 + tid) * W1]);
    }
    __syncthreads();

    const int ip  = tid & 15;          // i pair
    const int bp  = (tid >> 4) & 7;    // batch pair
    const int kh  = tid >> 7;          // k half
    const int ip2 = ip << 1;
    const int bp2 = bp << 1;
    const int jbase = kh << 8;
    const int w    = tid >> 5;         // staging warp
    const int lane = tid & 31;

    for (int t = 0; t < T_; ++t) {
        const int rpar = t & 1, wpar = rpar ^ 1;

        // --- reconstruct f_{t-1}[b] + stage x_t ---
        if (tid < 16) {
            int b = bb0 + tid;
            float f = 0.0f;
            if (t > 0) {
                f = g_fbase[(t - 1) * B_ + b];
                const float* fp = g_fp[rpar ^ 1] + b * 16;
#pragma unroll
                for (int k = 0; k < 16; ++k) f += __ldcg(&fp[k]);
            }
            fs[tid] = f;
            xb[tid] = __ldg(&x[(size_t)b * T_ + t]);
        }
        __syncthreads();

        // --- stage c_eff = c-hat + f*B_{t-1}, and h_{t-1} (stride-18 rows) ---
        {
            int tb = (t > 0) ? (t - 1) : 0;
            const float* Bp = B_st + (size_t)tb * N_;
#pragma unroll
            for (int s2 = 0; s2 < 2; ++s2) {
                int bl = 2 * w + s2;
                int b  = bb0 + bl;
                const float* crow = g_c[rpar] + (size_t)b * N_;
                const float* hrow = (t == 0) ? (h0 + (size_t)b * N_)
                                             : (out + ((size_t)b * T_ + (t - 1)) * N_);
                float fb = fs[bl];
#pragma unroll 8
                for (int k = 0; k < 16; ++k) {
                    int j = k * 32 + lane;
                    cs[j * 18 + bl] = __ldcg(&crow[j]) + fb * __ldg(&Bp[j]);
                    hs[j * 18 + bl] = __ldcg(&hrow[j]);
                }
            }
        }
        __syncthreads();

        // --- main dots (f32x2, i-pair packed), A prefetch ring depth 8 ---
        const ull* pa = (const ull*)(g_AT + (size_t)t * (N_ * N_)
                                     + (size_t)jbase * N_) + ((i0 + ip2) >> 1);
        ull ar[8];
#pragma unroll
        for (int k = 0; k < 8; ++k) ar[k] = __ldg(pa + (size_t)k * 256);

        ull ag0 = 0, ag1 = 0, aa0 = 0, aa1 = 0;
        for (int jc = 0; jc < 256; jc += 8) {
#pragma unroll
            for (int k = 0; k < 8; ++k) {
                int j = jbase + jc + k;
                ull a2 = ar[k];
                if (jc + 8 < 256) ar[k] = __ldg(pa + (size_t)(jc + 8 + k) * 256);
                ull wi2 = *(const ull*)&WiT_s[j * 32 + ip2];
                ull wh2 = *(const ull*)&WhT_s[j * 32 + ip2];
                ull c01 = *(const ull*)&cs[j * 18 + bp2];
                ull h01 = *(const ull*)&hs[j * 18 + bp2];
                float c0, c1, h0v, h1v;
                unpack2(c01, c0, c1);
                unpack2(h01, h0v, h1v);
                ull c0s = splat2(c0), c1s = splat2(c1);
                ull h0s = splat2(h0v), h1s = splat2(h1v);
                ag0 = fma2(wi2, c0s, ag0); ag0 = fma2(wh2, h0s, ag0);
                ag1 = fma2(wi2, c1s, ag1); ag1 = fma2(wh2, h1s, ag1);
                aa0 = fma2(a2, c0s, aa0);
                aa1 = fma2(a2, c1s, aa1);
            }
        }

        // --- k-split reduction ---
        if (kh == 1) {
            ull* r = red_u + (tid - 128) * 4;
            r[0] = ag0; r[1] = ag1; r[2] = aa0; r[3] = aa1;
        }
        __syncthreads();

        if (kh == 0) {
            const ull* r = red_u + tid * 4;
            ag0 = add2(ag0, r[0]); ag1 = add2(ag1, r[1]);
            aa0 = add2(aa0, r[2]); aa1 = add2(aa1, r[3]);

            int ie = i0 + ip2, io = ie + 1;
            int b0g = bb0 + bp2, b1g = b0g + 1;
            float xb0 = xb[bp2], xb1 = xb[bp2 + 1];
            float be = bias_s[ip2], bo = bias_s[ip2 + 1];
            float we = w0_s[ip2],  wo = w0_s[ip2 + 1];

            float g0e, g0o, g1e, g1o;
            unpack2(ag0, g0e, g0o);
            unpack2(ag1, g1e, g1o);
            g0e += be + we * xb0;  g0o += bo + wo * xb0;
            g1e += be + we * xb1;  g1o += bo + wo * xb1;

            float o0e = 1.0f / (1.0f + __expf(-g0e));
            float o0o = 1.0f / (1.0f + __expf(-g0o));
            float o1e = 1.0f / (1.0f + __expf(-g1e));
            float o1o = 1.0f / (1.0f + __expf(-g1o));

            float hn0e = o0e * tanhf(cs[ie * 18 + bp2]);
            float hn0o = o0o * tanhf(cs[io * 18 + bp2]);
            float hn1e = o1e * tanhf(cs[ie * 18 + bp2 + 1]);
            float hn1o = o1o * tanhf(cs[io * 18 + bp2 + 1]);

            out[((size_t)b0g * T_ + t) * N_ + ie] = hn0e;
            out[((size_t)b0g * T_ + t) * N_ + io] = hn0o;
            out[((size_t)b1g * T_ + t) * N_ + ie] = hn1e;
            out[((size_t)b1g * T_ + t) * N_ + io] = hn1o;

            redf[bp2 * 32 + ip2]           = wf_s[ip2]     * hn0e;
            redf[bp2 * 32 + ip2 + 1]       = wf_s[ip2 + 1] * hn0o;
            redf[(bp2 + 1) * 32 + ip2]     = wf_s[ip2]     * hn1e;
            redf[(bp2 + 1) * 32 + ip2 + 1] = wf_s[ip2 + 1] * hn1o;

            float a0e, a0o, a1e, a1o;
            unpack2(aa0, a0e, a0o);
            unpack2(aa1, a1e, a1o);
            __stcg(&g_c[wpar][(size_t)b0g * N_ + ie], a0e);
            __stcg(&g_c[wpar][(size_t)b0g * N_ + io], a0o);
            __stcg(&g_c[wpar][(size_t)b1g * N_ + ie], a1e);
            __stcg(&g_c[wpar][(size_t)b1g * N_ + io], a1o);
        }
        __syncthreads();

        // --- per-block f partial (deterministic order) ---
        if (tid < 16) {
            float s = 0.0f;
#pragma unroll
            for (int k = 0; k < 32; ++k) s += redf[tid * 32 + k];
            __stcg(&g_fp[t & 1][(bb0 + tid) * 16 + it], s);
        }

        if (t != T_ - 1) grid_barrier();
    }
}

// ---------------------------------------------------------------------------
// Final: c_f = c-hat_{511} + f_{511} * B_{511}
// ---------------------------------------------------------------------------
__global__ void k_final(const float* __restrict__ B_st, float* __restrict__ outc) {
    int idx = blockIdx.x * blockDim.x + threadIdx.x;
    if (idx >= B_ * N_) return;
    int b = idx >> 9, i = idx & 511;
    float f = g_fbase[(T_ - 1) * B_ + b];
#pragma unroll
    for (int k = 0; k < 16; ++k) f += g_fp[1][b * 16 + k];
    outc[idx] = g_c[0][idx] + f * __ldg(&B_st[(size_t)(T_ - 1) * N_ + i]);
}

extern "C" void kernel_launch(void* const* d_in, const int* in_sizes, int n_in,
                              void* d_out, int out_size) {
    const float* x  = (const float*)d_in[0];
    const float* h0 = (const float*)d_in[1];
    const float* c0 = (const float*)d_in[2];
    const float* Wi = (const float*)d_in[3];
    const float* bi = (const float*)d_in[4];
    const float* Wh = (const float*)d_in[5];
    const float* bh = (const float*)d_in[6];
    const float* Wf = (const float*)d_in[7];
    const float* bf = (const float*)d_in[8];
    const float* A  = (const float*)d_in[9];
    const float* Bs = (const float*)d_in[10];
    float* out = (float*)d_out;

    cudaFuncSetAttribute(hippo_main, cudaFuncAttributeMaxDynamicSharedMemorySize, SMEM_BYTES);

    k_transpose<<<dim3(16, 16, 512), dim3(32, 8)>>>(A);
    k_wtrans<<<dim3(16, 16, 2), dim3(32, 8)>>>(Wi, Wh);
    k_init<<<256, 256>>>(x, c0, Wf, bf);
    hippo_main<<<NBLK, NTHR, SMEM_BYTES>>>(x, h0, Wi, bi, Wh, bh, Wf, Bs, out);
    k_final<<<256, 256>>>(Bs, out + (size_t)B_ * T_ * N_);
}

// round 6
// speedup vs baseline: 4.7162x; 1.5586x over previous
#include <cuda_runtime.h>
#include <cuda_bf16.h>
#include <cstdint>
#include <cstddef>

#define T_ 512
#define N_ 512
#define B_ 128
#define W1 513
#define NBLK 128
#define NTHR 256

typedef unsigned long long ull;

// shared memory layout (float offsets)
#define SM_WI   0        // [512 j][32 i]                      16384 f
#define SM_WH   16384    // [512 j][32 i]                      16384 f
#define SM_ST   32768    // [8 bg][512 j][4 {c0,c1,h0,h1}] pad 16416 f (stride 2052/bg)
#define SM_RED  49184    // 192 thr x 16 f                      3072 f
#define SM_REDF 52256    // [16 b][8 ig]                         128 f
#define SM_FS   52384    // 16
#define SM_XB   52400    // 16
#define SM_WF   52416    // 32
#define SM_BIAS 52448    // 32
#define SM_W0   52480    // 32
#define SM_FLOATS 52512
#define SMEM_BYTES (SM_FLOATS * 4)   // 210,048 B

#define ST_BG 2052       // float stride per bg section (8208 B, 16B-aligned, bank-offset 4)

// device scratch (static arrays: allocation-free)
__device__ float g_AT[(size_t)T_ * N_ * N_];   // A transposed: [t][j][i]
__device__ float g_WiT[(size_t)N_ * N_];       // Wi transposed: [j][i] (cols 1..512)
__device__ float g_WhT[(size_t)N_ * N_];
__device__ float g_c[2][(size_t)B_ * N_];      // double-buffered c-hat, [b][j]
__device__ float g_fp[2][B_ * 16];             // f partials [parity][b][i_tile]
__device__ float g_fbase[T_ * B_];             // bf + Wf0 * x[b,t]
__device__ unsigned g_arrive;
__device__ volatile unsigned g_gen;

// ---- f32x2 helpers ----
__device__ __forceinline__ ull pack2(float a, float b) {
    ull r; asm("mov.b64 %0, {%1, %2};" : "=l"(r) : "f"(a), "f"(b)); return r;
}
__device__ __forceinline__ void unpack2(ull v, float& a, float& b) {
    asm("mov.b64 {%0, %1}, %2;" : "=f"(a), "=f"(b) : "l"(v));
}
__device__ __forceinline__ ull splat2(float a) {
    ull r; asm("mov.b64 %0, {%1, %1};" : "=l"(r) : "f"(a)); return r;
}
__device__ __forceinline__ ull fma2(ull a, ull b, ull c) {
    ull d; asm("fma.rn.f32x2 %0, %1, %2, %3;" : "=l"(d) : "l"(a), "l"(b), "l"(c)); return d;
}
__device__ __forceinline__ ull add2(ull a, ull b) {
    ull d; asm("add.rn.f32x2 %0, %1, %2;" : "=l"(d) : "l"(a), "l"(b)); return d;
}

__device__ __forceinline__ void grid_barrier() {
    __syncthreads();
    if (threadIdx.x == 0) {
        unsigned old = g_gen;
        __threadfence();
        if (atomicAdd(&g_arrive, 1u) == (unsigned)(NBLK - 1)) {
            atomicExch(&g_arrive, 0u);
            __threadfence();
            g_gen = old + 1u;
        } else {
            while (g_gen == old) { }
        }
    }
    __syncthreads();
    __threadfence();
}

// ---------------------------------------------------------------------------
// Pre-pass: transpose A_stack[t][i][j] -> g_AT[t][j][i]
// ---------------------------------------------------------------------------
__global__ void k_transpose(const float* __restrict__ A) {
    __shared__ float tile[32][33];
    int t  = blockIdx.z;
    int j0 = blockIdx.x << 5, i0 = blockIdx.y << 5;
    int tx = threadIdx.x, ty = threadIdx.y;
    const float* src = A + ((size_t)t * N_ + i0) * N_ + j0;
#pragma unroll
    for (int r = 0; r < 4; ++r)
        tile[ty + r * 8][tx] = src[(size_t)(ty + r * 8) * N_ + tx];
    __syncthreads();
    float* dst = g_AT + ((size_t)t * N_ + j0) * N_ + i0;
#pragma unroll
    for (int r = 0; r < 4; ++r)
        dst[(size_t)(ty + r * 8) * N_ + tx] = tile[tx][ty + r * 8];
}

// ---------------------------------------------------------------------------
// Pre-pass: transpose gate weights Wi/Wh[i][1+j] -> g_W*T[j][i]
// ---------------------------------------------------------------------------
__global__ void k_wtrans(const float* __restrict__ Wi, const float* __restrict__ Wh) {
    __shared__ float tile[32][33];
    const float* W = blockIdx.z ? Wh : Wi;
    float* WT = blockIdx.z ? g_WhT : g_WiT;
    int j0 = blockIdx.x << 5, i0 = blockIdx.y << 5;
    int tx = threadIdx.x, ty = threadIdx.y;
#pragma unroll
    for (int r = 0; r < 4; ++r)
        tile[ty + r * 8][tx] = W[(size_t)(i0 + ty + r * 8) * W1 + 1 + j0 + tx];
    __syncthreads();
#pragma unroll
    for (int r = 0; r < 4; ++r)
        WT[(size_t)(j0 + ty + r * 8) * N_ + i0 + tx] = tile[tx][ty + r * 8];
}

// ---------------------------------------------------------------------------
// Pre-pass: per-launch re-init of mutable state (graph-replay safe)
// ---------------------------------------------------------------------------
__global__ void k_init(const float* __restrict__ x, const float* __restrict__ c0,
                       const float* __restrict__ Wf, const float* __restrict__ bf) {
    int idx = blockIdx.x * blockDim.x + threadIdx.x;
    if (idx < B_ * N_) g_c[0][idx] = c0[idx];
    if (idx < T_ * B_) {
        int t = idx >> 7, b = idx & 127;
        g_fbase[idx] = __ldg(&bf[0]) + __ldg(&Wf[0]) * __ldg(&x[(size_t)b * T_ + t]);
    }
    if (idx < B_ * 16) g_fp[1][idx] = 0.0f;
}

// ---------------------------------------------------------------------------
// Main persistent kernel: 128 blocks x 256 threads.
// block = (it in [0,16): 32 i-cols) x (bt in [0,8): 16 batches)
// thread: kq = warp>>1 (k-interleave j=4jj+kq), ig = lane&7 (4-i group),
//         bgl = (lane>>3) + 4*(warp&1)  (b-pair)
// ---------------------------------------------------------------------------
__global__ void __launch_bounds__(NTHR, 1)
hippo_main(const float* __restrict__ x,  const float* __restrict__ h0,
           const float* __restrict__ Wi, const float* __restrict__ bi,
           const float* __restrict__ Wh, const float* __restrict__ bh,
           const float* __restrict__ Wf, const float* __restrict__ B_st,
           float* __restrict__ out) {
    extern __shared__ float sm[];
    float* fs     = sm + SM_FS;
    float* xb     = sm + SM_XB;
    float* wf_s   = sm + SM_WF;
    float* bias_s = sm + SM_BIAS;
    float* w0_s   = sm + SM_W0;
    float* redf   = sm + SM_REDF;

    const int tid = threadIdx.x;
    const int it  = blockIdx.x >> 3;
    const int bt  = blockIdx.x & 7;
    const int i0  = it << 5;
    const int bb0 = bt << 4;

    // one-time weight staging (coalesced LDG, conflict-free STS)
    for (int idx = tid; idx < 512 * 32; idx += NTHR) {
        int j = idx >> 5, iL = idx & 31;
        sm[SM_WI + idx] = __ldg(&g_WiT[(size_t)j * N_ + i0 + iL]);
        sm[SM_WH + idx] = __ldg(&g_WhT[(size_t)j * N_ + i0 + iL]);
    }
    if (tid < 32) {
        wf_s[tid]   = __ldg(&Wf[1 + i0 + tid]);
        bias_s[tid] = __ldg(&bi[i0 + tid]) + __ldg(&bh[i0 + tid]);
        w0_s[tid]   = __ldg(&Wi[(size_t)(i0 + tid) * W1]) + __ldg(&Wh[(size_t)(i0 + tid) * W1]);
    }
    __syncthreads();

    const int lane = tid & 31;
    const int w    = tid >> 5;
    const int kq   = w >> 1;
    const int ig   = lane & 7;
    const int bgl  = (lane >> 3) + ((w & 1) << 2);
    const int sb   = w;                 // staging b-pair role

    const float* wiP = sm + SM_WI + kq * 32 + ig * 4;
    const float* whP = sm + SM_WH + kq * 32 + ig * 4;
    const float* stP = sm + SM_ST + bgl * ST_BG + kq * 4;

    for (int t = 0; t < T_; ++t) {
        const int rpar = t & 1, wpar = rpar ^ 1;

        // A prefetch ring for this step (issued before staging to bury latency)
        const float4* pa = (const float4*)(g_AT + (size_t)t * (N_ * N_)
                                           + (size_t)kq * N_ + (i0 + ig * 4));
        float4 ar[8];
#pragma unroll
        for (int k = 0; k < 8; ++k) ar[k] = __ldg(pa + (size_t)k * 512);

        // --- reconstruct f_{t-1}[b] + stage x_t ---
        if (tid < 16) {
            int b = bb0 + tid;
            float f = 0.0f;
            if (t > 0) {
                f = g_fbase[(t - 1) * B_ + b];
                const float* fp = g_fp[rpar ^ 1] + b * 16;
#pragma unroll
                for (int k = 0; k < 16; ++k) f += __ldcg(&fp[k]);
            }
            fs[tid] = f;
            xb[tid] = __ldg(&x[(size_t)b * T_ + t]);
        }
        __syncthreads();

        // --- stage interleaved state {c_eff0, c_eff1, h0, h1} per (bg, j) ---
        {
            int tb = (t > 0) ? (t - 1) : 0;
            const float* Bp = B_st + (size_t)tb * N_;
            int b0 = bb0 + sb * 2, b1 = b0 + 1;
            const float* c0r = g_c[rpar] + (size_t)b0 * N_;
            const float* c1r = g_c[rpar] + (size_t)b1 * N_;
            const float* h0r = (t == 0) ? (h0 + (size_t)b0 * N_)
                                        : (out + ((size_t)b0 * T_ + (t - 1)) * N_);
            const float* h1r = (t == 0) ? (h0 + (size_t)b1 * N_)
                                        : (out + ((size_t)b1 * T_ + (t - 1)) * N_);
            float f0 = fs[sb * 2], f1 = fs[sb * 2 + 1];
            float* dst = sm + SM_ST + sb * ST_BG;
#pragma unroll 4
            for (int kk = 0; kk < 16; ++kk) {
                int j = kk * 32 + lane;
                float bj = __ldg(&Bp[j]);
                float4 v;
                v.x = __ldcg(&c0r[j]) + f0 * bj;
                v.y = __ldcg(&c1r[j]) + f1 * bj;
                v.z = __ldcg(&h0r[j]);
                v.w = __ldcg(&h1r[j]);
                *(float4*)(dst + j * 4) = v;
            }
        }
        __syncthreads();

        // --- main dots: 4i x 2b per thread, k-interleaved j = 4jj + kq ---
        ull ag00 = 0, ag01 = 0, ag10 = 0, ag11 = 0;
        ull aa00 = 0, aa01 = 0, aa10 = 0, aa11 = 0;
        for (int jc = 0; jc < 128; jc += 8) {
#pragma unroll
            for (int k = 0; k < 8; ++k) {
                float4 a4 = ar[k];
                if (jc + 8 < 128) ar[k] = __ldg(pa + (size_t)(jc + 8 + k) * 512);
                int jj = jc + k;
                ull wiL = *(const ull*)(wiP + jj * 128);
                ull wiH = *(const ull*)(wiP + jj * 128 + 2);
                ull whL = *(const ull*)(whP + jj * 128);
                ull whH = *(const ull*)(whP + jj * 128 + 2);
                float4 st = *(const float4*)(stP + jj * 16);
                ull c0s = splat2(st.x), c1s = splat2(st.y);
                ull h0s = splat2(st.z), h1s = splat2(st.w);
                ull aL = pack2(a4.x, a4.y), aH = pack2(a4.z, a4.w);
                ag00 = fma2(wiL, c0s, ag00); ag00 = fma2(whL, h0s, ag00);
                ag01 = fma2(wiH, c0s, ag01); ag01 = fma2(whH, h0s, ag01);
                ag10 = fma2(wiL, c1s, ag10); ag10 = fma2(whL, h1s, ag10);
                ag11 = fma2(wiH, c1s, ag11); ag11 = fma2(whH, h1s, ag11);
                aa00 = fma2(aL, c0s, aa00);  aa01 = fma2(aH, c0s, aa01);
                aa10 = fma2(aL, c1s, aa10);  aa11 = fma2(aH, c1s, aa11);
            }
        }

        // --- k-split reduction: quarters 1..3 dump, quarter 0 reduces ---
        if (tid >= 64) {
            ull* r = (ull*)(sm + SM_RED + (tid - 64) * 16);
            r[0] = ag00; r[1] = ag01; r[2] = ag10; r[3] = ag11;
            r[4] = aa00; r[5] = aa01; r[6] = aa10; r[7] = aa11;
        }
        __syncthreads();

        if (tid < 64) {
#pragma unroll
            for (int q = 0; q < 3; ++q) {
                const ull* r = (const ull*)(sm + SM_RED + (q * 64 + tid) * 16);
                ag00 = add2(ag00, r[0]); ag01 = add2(ag01, r[1]);
                ag10 = add2(ag10, r[2]); ag11 = add2(ag11, r[3]);
                aa00 = add2(aa00, r[4]); aa01 = add2(aa01, r[5]);
                aa10 = add2(aa10, r[6]); aa11 = add2(aa11, r[7]);
            }
            int ib  = i0 + ig * 4;
            int b0  = bb0 + bgl * 2, b1 = b0 + 1;
            float xb0 = xb[bgl * 2], xb1 = xb[bgl * 2 + 1];
            float gb0[4], gb1[4], hv0[4], hv1[4];
            unpack2(ag00, gb0[0], gb0[1]); unpack2(ag01, gb0[2], gb0[3]);
            unpack2(ag10, gb1[0], gb1[1]); unpack2(ag11, gb1[2], gb1[3]);
#pragma unroll
            for (int r = 0; r < 4; ++r) {
                float bsv = bias_s[ig * 4 + r], w0v = w0_s[ig * 4 + r];
                float gg0 = gb0[r] + bsv + w0v * xb0;
                float gg1 = gb1[r] + bsv + w0v * xb1;
                float o0 = 1.0f / (1.0f + __expf(-gg0));
                float o1 = 1.0f / (1.0f + __expf(-gg1));
                float ce0 = sm[SM_ST + bgl * ST_BG + (ib + r) * 4 + 0];
                float ce1 = sm[SM_ST + bgl * ST_BG + (ib + r) * 4 + 1];
                hv0[r] = o0 * tanhf(ce0);
                hv1[r] = o1 * tanhf(ce1);
            }
            *(float4*)&out[((size_t)b0 * T_ + t) * N_ + ib] =
                make_float4(hv0[0], hv0[1], hv0[2], hv0[3]);
            *(float4*)&out[((size_t)b1 * T_ + t) * N_ + ib] =
                make_float4(hv1[0], hv1[1], hv1[2], hv1[3]);

            float fa0 = wf_s[ig*4]*hv0[0] + wf_s[ig*4+1]*hv0[1]
                      + wf_s[ig*4+2]*hv0[2] + wf_s[ig*4+3]*hv0[3];
            float fa1 = wf_s[ig*4]*hv1[0] + wf_s[ig*4+1]*hv1[1]
                      + wf_s[ig*4+2]*hv1[2] + wf_s[ig*4+3]*hv1[3];
            redf[(bgl * 2) * 8 + ig]     = fa0;
            redf[(bgl * 2 + 1) * 8 + ig] = fa1;

            float ca0[4], ca1[4];
            unpack2(aa00, ca0[0], ca0[1]); unpack2(aa01, ca0[2], ca0[3]);
            unpack2(aa10, ca1[0], ca1[1]); unpack2(aa11, ca1[2], ca1[3]);
            __stcg((float4*)&g_c[wpar][(size_t)b0 * N_ + ib],
                   make_float4(ca0[0], ca0[1], ca0[2], ca0[3]));
            __stcg((float4*)&g_c[wpar][(size_t)b1 * N_ + ib],
                   make_float4(ca1[0], ca1[1], ca1[2], ca1[3]));
        }
        __syncthreads();

        // --- per-block f partial (deterministic order) ---
        if (tid < 16) {
            float s = 0.0f;
#pragma unroll
            for (int k = 0; k < 8; ++k) s += redf[tid * 8 + k];
            __stcg(&g_fp[t & 1][(bb0 + tid) * 16 + it], s);
        }

        if (t != T_ - 1) grid_barrier();
    }
}

// ---------------------------------------------------------------------------
// Final: c_f = c-hat_{511} + f_{511} * B_{511}
// ---------------------------------------------------------------------------
__global__ void k_final(const float* __restrict__ B_st, float* __restrict__ outc) {
    int idx = blockIdx.x * blockDim.x + threadIdx.x;
    if (idx >= B_ * N_) return;
    int b = idx >> 9, i = idx & 511;
    float f = g_fbase[(T_ - 1) * B_ + b];
#pragma unroll
    for (int k = 0; k < 16; ++k) f += g_fp[1][b * 16 + k];
    outc[idx] = g_c[0][idx] + f * __ldg(&B_st[(size_t)(T_ - 1) * N_ + i]);
}

extern "C" void kernel_launch(void* const* d_in, const int* in_sizes, int n_in,
                              void* d_out, int out_size) {
    const float* x  = (const float*)d_in[0];
    const float* h0 = (const float*)d_in[1];
    const float* c0 = (const float*)d_in[2];
    const float* Wi = (const float*)d_in[3];
    const float* bi = (const float*)d_in[4];
    const float* Wh = (const float*)d_in[5];
    const float* bh = (const float*)d_in[6];
    const float* Wf = (const float*)d_in[7];
    const float* bf = (const float*)d_in[8];
    const float* A  = (const float*)d_in[9];
    const float* Bs = (const float*)d_in[10];
    float* out = (float*)d_out;

    cudaFuncSetAttribute(hippo_main, cudaFuncAttributeMaxDynamicSharedMemorySize, SMEM_BYTES);

    k_transpose<<<dim3(16, 16, 512), dim3(32, 8)>>>(A);
    k_wtrans<<<dim3(16, 16, 2), dim3(32, 8)>>>(Wi, Wh);
    k_init<<<256, 256>>>(x, c0, Wf, bf);
    hippo_main<<<NBLK, NTHR, SMEM_BYTES>>>(x, h0, Wi, bi, Wh, bh, Wf, Bs, out);
    k_final<<<256, 256>>>(Bs, out + (size_t)B_ * T_ * N_);
}

// round 9
// speedup vs baseline: 6.1107x; 1.2957x over previous
#include <cuda_runtime.h>
#include <cuda_bf16.h>
#include <cstdint>
#include <cstddef>

#define T_ 512
#define N_ 512
#define B_ 128
#define W1 513
#define NBLK 128
#define NTHR 256

typedef unsigned long long ull;

// shared memory layout (float offsets)
#define SM_WI   0        // [128 j4][32 i][4]   16384
#define SM_WH   16384    // [128 j4][32 i][4]   16384
#define SM_CS   32768    // [16 b][520 j]        8320
#define SM_HS   41088    // [16 b][520 j]        8320
#define SM_REDA 49408    // 2048 ull             4096
#define SM_REDB 53504    // 1024 ull             2048
#define SM_REDC 55552    //  512 ull             1024
#define SM_REDF 56576    // [16 b][8 ig]          128
#define SM_FS   56704
#define SM_XB   56720
#define SM_WFS  56736
#define SM_BIAS 56768
#define SM_W0S  56800
#define SM_FLOATS 56832
#define SMEM_BYTES (SM_FLOATS * 4)   // 227,328 B

// device scratch (static arrays: allocation-free)
__device__ float g_A4[(size_t)T_ * N_ * N_];   // [t][j/4][i][j%4]
__device__ float g_Wi4[(size_t)N_ * N_];       // [j/4][i][j%4] (gate cols 1..512)
__device__ float g_Wh4[(size_t)N_ * N_];
__device__ float g_c[2][(size_t)B_ * N_];      // double-buffered c-hat, [b][j]
__device__ float g_fp[2][B_ * 16];             // f partials [parity][b][i_tile]
__device__ float g_fbase[T_ * B_];             // bf + Wf0 * x[b,t]
__device__ unsigned g_arrive;
__device__ volatile unsigned g_gen;

// ---- f32x2 helpers ----
__device__ __forceinline__ ull pack2(float a, float b) {
    ull r; asm("mov.b64 %0, {%1, %2};" : "=l"(r) : "f"(a), "f"(b)); return r;
}
__device__ __forceinline__ void unpack2(ull v, float& a, float& b) {
    asm("mov.b64 {%0, %1}, %2;" : "=f"(a), "=f"(b) : "l"(v));
}
__device__ __forceinline__ ull fma2(ull a, ull b, ull c) {
    ull d; asm("fma.rn.f32x2 %0, %1, %2, %3;" : "=l"(d) : "l"(a), "l"(b), "l"(c)); return d;
}
__device__ __forceinline__ ull add2(ull a, ull b) {
    ull d; asm("add.rn.f32x2 %0, %1, %2;" : "=l"(d) : "l"(a), "l"(b)); return d;
}

__device__ __forceinline__ void grid_barrier() {
    __syncthreads();
    if (threadIdx.x == 0) {
        unsigned old = g_gen;
        __threadfence();
        if (atomicAdd(&g_arrive, 1u) == (unsigned)(NBLK - 1)) {
            atomicExch(&g_arrive, 0u);
            __threadfence();
            g_gen = old + 1u;
        } else {
            while (g_gen == old) { }
        }
    }
    __syncthreads();
    __threadfence();
}

// ---------------------------------------------------------------------------
// Pre-pass: repack A_stack[t][i][j] -> g_A4[t][j/4][i][j%4]
// ---------------------------------------------------------------------------
__global__ void k_apack(const float* __restrict__ A) {
    __shared__ float tile[32][33];
    int t  = blockIdx.z;
    int j0 = blockIdx.x << 5, i0 = blockIdx.y << 5;
    int tx = threadIdx.x, ty = threadIdx.y;
    const float* src = A + ((size_t)t * N_ + i0) * N_ + j0;
#pragma unroll
    for (int r = 0; r < 4; ++r)
        tile[ty + r * 8][tx] = src[(size_t)(ty + r * 8) * N_ + tx];
    __syncthreads();
#pragma unroll
    for (int r = 0; r < 4; ++r) {
        int e   = (ty * 32 + tx) + (r << 8);   // 0..1023
        int j4L = e >> 7;
        int rem = e & 127;
        int iL  = rem >> 2;
        int k   = e & 3;
        g_A4[(((size_t)t * 128 + (j0 >> 2) + j4L) * 512 + i0 + iL) * 4 + k]
            = tile[iL][j4L * 4 + k];
    }
}

// ---------------------------------------------------------------------------
// Pre-pass: repack gate weights W[i][1+j] -> [j/4][i][j%4]
// ---------------------------------------------------------------------------
__global__ void k_wpack(const float* __restrict__ Wi, const float* __restrict__ Wh) {
    int idx = blockIdx.x * 256 + threadIdx.x;
    if (idx >= 2 * N_ * N_) return;
    int wsel = idx >= N_ * N_;
    int e = idx - wsel * N_ * N_;
    int j4 = e >> 11, rem = e & 2047;
    int i = rem >> 2, k = e & 3;
    const float* W = wsel ? Wh : Wi;
    float* dst = wsel ? g_Wh4 : g_Wi4;
    dst[e] = W[(size_t)i * W1 + 1 + j4 * 4 + k];
}

// ---------------------------------------------------------------------------
// Pre-pass: per-launch re-init of mutable state (graph-replay safe)
// ---------------------------------------------------------------------------
__global__ void k_init(const float* __restrict__ x, const float* __restrict__ c0,
                       const float* __restrict__ Wf, const float* __restrict__ bf) {
    int idx = blockIdx.x * blockDim.x + threadIdx.x;
    if (idx < B_ * N_) g_c[0][idx] = c0[idx];
    if (idx < T_ * B_) {
        int t = idx >> 7, b = idx & 127;
        g_fbase[idx] = __ldg(&bf[0]) + __ldg(&Wf[0]) * __ldg(&x[(size_t)b * T_ + t]);
    }
}

// ---------------------------------------------------------------------------
// Main persistent kernel: 128 blocks x 256 threads.
// block = (it: 32 i-cols) x (bt: 16 batches)
// warp w = kq (k-eighth, j in [64kq, 64kq+64)); lane: ig = lane&7, bg = lane>>3
// thread outputs: i = i0 + ig + 8r (r<4), b = bb0 + bg + 4s (s<4)
// ---------------------------------------------------------------------------
__global__ void __launch_bounds__(NTHR, 1)
hippo_main(const float* __restrict__ x,  const float* __restrict__ h0,
           const float* __restrict__ Wi, const float* __restrict__ bi,
           const float* __restrict__ Wh, const float* __restrict__ bh,
           const float* __restrict__ Wf, const float* __restrict__ B_st,
           float* __restrict__ out) {
    extern __shared__ float sm[];
    float* fs     = sm + SM_FS;
    float* xb     = sm + SM_XB;
    float* wf_s   = sm + SM_WFS;
    float* bias_s = sm + SM_BIAS;
    float* w0_s   = sm + SM_W0S;
    float* redf   = sm + SM_REDF;

    const int tid = threadIdx.x;
    const int it  = blockIdx.x >> 3;
    const int bt  = blockIdx.x & 7;
    const int i0  = it << 5;
    const int bb0 = bt << 4;

    // one-time weight staging (packed layout; fully coalesced both sides)
    for (int s = tid; s < 16384; s += NTHR) {
        int j4 = s >> 7, rem = s & 127;
        sm[SM_WI + s] = __ldg(&g_Wi4[(size_t)j4 * 2048 + i0 * 4 + rem]);
        sm[SM_WH + s] = __ldg(&g_Wh4[(size_t)j4 * 2048 + i0 * 4 + rem]);
    }
    if (tid < 32) {
        wf_s[tid]   = __ldg(&Wf[1 + i0 + tid]);
        bias_s[tid] = __ldg(&bi[i0 + tid]) + __ldg(&bh[i0 + tid]);
        w0_s[tid]   = __ldg(&Wi[(size_t)(i0 + tid) * W1]) + __ldg(&Wh[(size_t)(i0 + tid) * W1]);
    }
    __syncthreads();

    const int lane = tid & 31;
    const int w    = tid >> 5;        // kq
    const int ig   = lane & 7;
    const int bg   = lane >> 3;
    const int j4b  = w << 4;          // first j4 of this warp's 64-j chunk

    for (int t = 0; t < T_; ++t) {
        const int rpar = t & 1, wpar = rpar ^ 1;

        // A prefetch (first j4 group) — issue before staging to bury latency
        const ulonglong2* pa = (const ulonglong2*)
            (g_A4 + ((size_t)t * 128 + j4b) * 2048 + (size_t)(i0 + ig) * 4);
        ulonglong2 av[2][4];
#pragma unroll
        for (int r = 0; r < 4; ++r) av[0][r] = __ldg(pa + r * 8);

        // --- reconstruct f_{t-1}[b] + stage x_t ---
        if (tid < 16) {
            int b = bb0 + tid;
            float f = 0.0f;
            if (t > 0) {
                f = g_fbase[(t - 1) * B_ + b];
                const float* fp = g_fp[rpar ^ 1] + b * 16;
#pragma unroll
                for (int k = 0; k < 16; ++k) f += __ldcg(&fp[k]);
            }
            fs[tid] = f;
            xb[tid] = __ldg(&x[(size_t)b * T_ + t]);
        }
        __syncthreads();

        // --- stage c_eff = c-hat + f*B_{t-1} and h_{t-1}; warp w -> b {2w,2w+1} ---
        {
            int tb = (t > 0) ? (t - 1) : 0;
            const float* Bp = B_st + (size_t)tb * N_;
#pragma unroll
            for (int s2 = 0; s2 < 2; ++s2) {
                int bl = 2 * w + s2;
                int b  = bb0 + bl;
                const float* crow = g_c[rpar] + (size_t)b * N_;
                const float* hrow = (t == 0) ? (h0 + (size_t)b * N_)
                                             : (out + ((size_t)b * T_ + (t - 1)) * N_);
                float fb = fs[bl];
#pragma unroll 8
                for (int kk = 0; kk < 16; ++kk) {
                    int j = kk * 32 + lane;
                    sm[SM_CS + bl * 520 + j] = __ldcg(&crow[j]) + fb * __ldg(&Bp[j]);
                    sm[SM_HS + bl * 520 + j] = __ldcg(&hrow[j]);
                }
            }
        }
        __syncthreads();

        // --- main dots: j-pair f32x2, no splats. 4i x 4b per thread, 16 j4 iters ---
        ull G[4][4], Aa[4][4];
#pragma unroll
        for (int r = 0; r < 4; ++r)
#pragma unroll
            for (int s = 0; s < 4; ++s) { G[r][s] = 0ull; Aa[r][s] = 0ull; }

        const ulonglong2* wiq0 = (const ulonglong2*)(sm + SM_WI + (size_t)j4b * 128 + ig * 4);
        const ulonglong2* whq0 = (const ulonglong2*)(sm + SM_WH + (size_t)j4b * 128 + ig * 4);
        const ulonglong2* csq0 = (const ulonglong2*)(sm + SM_CS + bg * 520 + j4b * 4);
        const ulonglong2* hsq0 = (const ulonglong2*)(sm + SM_HS + bg * 520 + j4b * 4);

#pragma unroll 2
        for (int q = 0; q < 16; ++q) {
            int cur = q & 1;
            if (q < 15) {
#pragma unroll
                for (int r = 0; r < 4; ++r)
                    av[cur ^ 1][r] = __ldg(pa + (size_t)(q + 1) * 512 + r * 8);
            }
            ulonglong2 cv[4], hv[4];
#pragma unroll
            for (int s = 0; s < 4; ++s) {
                cv[s] = csq0[q + s * 520];
                hv[s] = hsq0[q + s * 520];
            }
#pragma unroll
            for (int r = 0; r < 4; ++r) {
                ulonglong2 wi2 = wiq0[q * 32 + r * 8];
                ulonglong2 wh2 = whq0[q * 32 + r * 8];
                ulonglong2 a2  = av[cur][r];
#pragma unroll
                for (int s = 0; s < 4; ++s) {
                    G[r][s]  = fma2(wi2.x, cv[s].x, G[r][s]);
                    G[r][s]  = fma2(wi2.y, cv[s].y, G[r][s]);
                    G[r][s]  = fma2(wh2.x, hv[s].x, G[r][s]);
                    G[r][s]  = fma2(wh2.y, hv[s].y, G[r][s]);
                    Aa[r][s] = fma2(a2.x,  cv[s].x, Aa[r][s]);
                    Aa[r][s] = fma2(a2.y,  cv[s].y, Aa[r][s]);
                }
            }
        }

        // horizontal j-pair sums -> pack (gate, ahat) per output
        ull pk[16];
#pragma unroll
        for (int r = 0; r < 4; ++r)
#pragma unroll
            for (int s = 0; s < 4; ++s) {
                float ga, gb, aa, ab;
                unpack2(G[r][s], ga, gb);
                unpack2(Aa[r][s], aa, ab);
                pk[r * 4 + s] = pack2(ga + gb, aa + ab);
            }

        // --- 3-round cross-warp k reduction (interleaved [m][thread] layout) ---
        ull* redA = (ull*)(sm + SM_REDA);
        ull* redB = (ull*)(sm + SM_REDB);
        ull* redC = (ull*)(sm + SM_REDC);
        if (w >= 4) {
            int th = (w - 4) * 32 + lane;
#pragma unroll
            for (int m = 0; m < 16; ++m) redA[m * 128 + th] = pk[m];
        }
        __syncthreads();
        if (w < 4) {
            int th = w * 32 + lane;
#pragma unroll
            for (int m = 0; m < 16; ++m) pk[m] = add2(pk[m], redA[m * 128 + th]);
            if (w >= 2) {
                int t2 = (w - 2) * 32 + lane;
#pragma unroll
                for (int m = 0; m < 16; ++m) redB[m * 64 + t2] = pk[m];
            }
        }
        __syncthreads();
        if (w < 2) {
            int t2 = w * 32 + lane;
#pragma unroll
            for (int m = 0; m < 16; ++m) pk[m] = add2(pk[m], redB[m * 64 + t2]);
            if (w == 1) {
#pragma unroll
                for (int m = 0; m < 16; ++m) redC[m * 32 + lane] = pk[m];
            }
        }
        __syncthreads();

        // --- epilogue: warp 0 holds full sums for all 512 outputs of the block ---
        if (w == 0) {
#pragma unroll
            for (int m = 0; m < 16; ++m) pk[m] = add2(pk[m], redC[m * 32 + lane]);
#pragma unroll
            for (int s = 0; s < 4; ++s) {
                int bL = bg + 4 * s, bG = bb0 + bL;
                float xv = xb[bL];
                float fsum = 0.0f;
#pragma unroll
                for (int r = 0; r < 4; ++r) {
                    int iL = ig + 8 * r, iG = i0 + iL;
                    float gsum, asum;
                    unpack2(pk[r * 4 + s], gsum, asum);
                    float gate = gsum + bias_s[iL] + w0_s[iL] * xv;
                    float o = 1.0f / (1.0f + __expf(-gate));
                    float ce = sm[SM_CS + bL * 520 + iG];
                    float h = o * tanhf(ce);
                    out[((size_t)bG * T_ + t) * N_ + iG] = h;
                    fsum += wf_s[iL] * h;
                    __stcg(&g_c[wpar][(size_t)bG * N_ + iG], asum);
                }
                redf[bL * 8 + ig] = fsum;
            }
        }
        __syncthreads();

        // --- per-block f partial (deterministic order) ---
        if (tid < 16) {
            float sum = 0.0f;
#pragma unroll
            for (int k = 0; k < 8; ++k) sum += redf[tid * 8 + k];
            __stcg(&g_fp[t & 1][(bb0 + tid) * 16 + it], sum);
        }

        if (t != T_ - 1) grid_barrier();
    }
}

// ---------------------------------------------------------------------------
// Final: c_f = c-hat_{511} + f_{511} * B_{511}
// ---------------------------------------------------------------------------
__global__ void k_final(const float* __restrict__ B_st, float* __restrict__ outc) {
    int idx = blockIdx.x * blockDim.x + threadIdx.x;
    if (idx >= B_ * N_) return;
    int b = idx >> 9, i = idx & 511;
    float f = g_fbase[(T_ - 1) * B_ + b];
#pragma unroll
    for (int k = 0; k < 16; ++k) f += g_fp[1][b * 16 + k];
    outc[idx] = g_c[0][idx] + f * __ldg(&B_st[(size_t)(T_ - 1) * N_ + i]);
}

extern "C" void kernel_launch(void* const* d_in, const int* in_sizes, int n_in,
                              void* d_out, int out_size) {
    const float* x  = (const float*)d_in[0];
    const float* h0 = (const float*)d_in[1];
    const float* c0 = (const float*)d_in[2];
    const float* Wi = (const float*)d_in[3];
    const float* bi = (const float*)d_in[4];
    const float* Wh = (const float*)d_in[5];
    const float* bh = (const float*)d_in[6];
    const float* Wf = (const float*)d_in[7];
    const float* bf = (const float*)d_in[8];
    const float* A  = (const float*)d_in[9];
    const float* Bs = (const float*)d_in[10];
    float* out = (float*)d_out;

    cudaFuncSetAttribute(hippo_main, cudaFuncAttributeMaxDynamicSharedMemorySize, SMEM_BYTES);

    k_apack<<<dim3(16, 16, 512), dim3(32, 8)>>>(A);
    k_wpack<<<2048, 256>>>(Wi, Wh);
    k_init<<<256, 256>>>(x, c0, Wf, bf);
    hippo_main<<<NBLK, NTHR, SMEM_BYTES>>>(x, h0, Wi, bi, Wh, bh, Wf, Bs, out);
    k_final<<<256, 256>>>(Bs, out + (size_t)B_ * T_ * N_);
}